// round 5
// baseline (speedup 1.0000x reference)
#include <cuda_runtime.h>
#include <math.h>

#define BSZ   64
#define SEQ   256
#define MROWS (BSZ*SEQ)   // 16384
#define INF   1024
#define UFD   512
#define OFD   512

// Scratch (allocation-free rule: __device__ globals). ~96 MB, module-load time.
__device__ float g_D[MROWS*OFD];
__device__ float g_U[MROWS*OFD];
__device__ float g_E[MROWS*OFD];
__device__ float g_rowpart[BSZ*SEQ*4];  // tanh row sums, partial per r-tile
__device__ float g_colpart[BSZ*SEQ*4];  // tanh col sums, partial per s-tile

__device__ __forceinline__ float sigm(float x) { return 1.0f / (1.0f + expf(-x)); }

// Accumulate a 64x64 output tile: A is row-major [m, k] (k contiguous),
// B is "n-major" [n, k] (k contiguous) -> C += A * B^T.
// Aptr/Bptr are pre-offset to this thread's load element; both advance by k0.
__device__ __forceinline__ void gemm_acc_nmajor(
    const float* __restrict__ Aptr, const float* __restrict__ Bptr, int K,
    float (*As)[68], float (*Bs)[68],
    int lk, int lm, int m0, int n0, float acc[4][4])
{
    for (int k0 = 0; k0 < K; k0 += 16) {
        float4 av = *(const float4*)(Aptr + k0);
        float4 bv = *(const float4*)(Bptr + k0);
        __syncthreads();
        As[lk+0][lm] = av.x; As[lk+1][lm] = av.y; As[lk+2][lm] = av.z; As[lk+3][lm] = av.w;
        Bs[lk+0][lm] = bv.x; Bs[lk+1][lm] = bv.y; Bs[lk+2][lm] = bv.z; Bs[lk+3][lm] = bv.w;
        __syncthreads();
        #pragma unroll
        for (int k = 0; k < 16; k++) {
            float4 a = *(const float4*)(&As[k][m0]);
            float4 b = *(const float4*)(&Bs[k][n0]);
            float ar[4] = {a.x, a.y, a.z, a.w};
            float br[4] = {b.x, b.y, b.z, b.w};
            #pragma unroll
            for (int i = 0; i < 4; i++)
                #pragma unroll
                for (int j = 0; j < 4; j++)
                    acc[i][j] += ar[i] * br[j];
        }
    }
}

// ---------------------------------------------------------------------------
// Kernel 1: d = Xd*Wd^T + bd ; u = Xu*Wu^T + bu ; gating ; write g_D, g_U
// grid (OFD/64, MROWS/64), block 256
// ---------------------------------------------------------------------------
__global__ __launch_bounds__(256) void k_du(
    const float* __restrict__ Xd, const float* __restrict__ Xu,
    const float* __restrict__ Wd, const float* __restrict__ bd,
    const float* __restrict__ Wu, const float* __restrict__ bu)
{
    __shared__ float As[16][68];
    __shared__ float Bs[16][68];

    int tid = threadIdx.x;
    int tx = tid & 15, ty = tid >> 4;
    int m0 = ty * 4, n0 = tx * 4;
    int row0 = blockIdx.y * 64;
    int col0 = blockIdx.x * 64;

    int lm = tid >> 2;        // 0..63
    int lk = (tid & 3) * 4;   // 0,4,8,12

    float accd[4][4] = {};
    gemm_acc_nmajor(Xd + (size_t)(row0 + lm) * INF + lk,
                    Wd + (size_t)(col0 + lm) * INF + lk,
                    INF, As, Bs, lk, lm, m0, n0, accd);

    float accu[4][4] = {};
    gemm_acc_nmajor(Xu + (size_t)(row0 + lm) * UFD + lk,
                    Wu + (size_t)(col0 + lm) * UFD + lk,
                    UFD, As, Bs, lk, lm, m0, n0, accu);

    float4 bdv = *(const float4*)(bd + col0 + n0);
    float4 buv = *(const float4*)(bu + col0 + n0);
    float bdr[4] = {bdv.x, bdv.y, bdv.z, bdv.w};
    float bur[4] = {buv.x, buv.y, buv.z, buv.w};

    #pragma unroll
    for (int i = 0; i < 4; i++) {
        size_t base = (size_t)(row0 + m0 + i) * OFD + col0 + n0;
        float dv[4], uv[4];
        #pragma unroll
        for (int j = 0; j < 4; j++) {
            float d0 = accd[i][j] + bdr[j];
            float u0 = accu[i][j] + bur[j];
            float d1 = d0 * sigm(u0);
            float u1 = u0 * sigm(d1);
            dv[j] = d1; uv[j] = u1;
        }
        *(float4*)(g_D + base) = make_float4(dv[0], dv[1], dv[2], dv[3]);
        *(float4*)(g_U + base) = make_float4(uv[0], uv[1], uv[2], uv[3]);
    }
}

// ---------------------------------------------------------------------------
// Kernel 2: E = D @ W  (W row-major [k=512, n=512], no transpose)
// grid (OFD/64, MROWS/64), block 256
// ---------------------------------------------------------------------------
__global__ __launch_bounds__(256) void k_e(const float* __restrict__ W)
{
    __shared__ float As[16][68];
    __shared__ float Bs[16][68];

    int tid = threadIdx.x;
    int tx = tid & 15, ty = tid >> 4;
    int m0 = ty * 4, n0 = tx * 4;
    int row0 = blockIdx.y * 64;
    int col0 = blockIdx.x * 64;

    int lm  = tid >> 2;       // A loader: 0..63 rows
    int lk  = (tid & 3) * 4;  // A loader: k within tile
    int lkb = tid >> 4;       // B loader: 0..15 k rows
    int lnb = (tid & 15) * 4; // B loader: n within tile

    const float* Aptr = g_D + (size_t)(row0 + lm) * OFD + lk;
    const float* Bptr = W + (size_t)lkb * OFD + col0 + lnb;

    float acc[4][4] = {};
    for (int k0 = 0; k0 < OFD; k0 += 16) {
        float4 av = *(const float4*)(Aptr + k0);
        float4 bv = *(const float4*)(Bptr + (size_t)k0 * OFD);
        __syncthreads();
        As[lk+0][lm] = av.x; As[lk+1][lm] = av.y; As[lk+2][lm] = av.z; As[lk+3][lm] = av.w;
        *(float4*)(&Bs[lkb][lnb]) = bv;
        __syncthreads();
        #pragma unroll
        for (int k = 0; k < 16; k++) {
            float4 a = *(const float4*)(&As[k][m0]);
            float4 b = *(const float4*)(&Bs[k][n0]);
            float ar[4] = {a.x, a.y, a.z, a.w};
            float br[4] = {b.x, b.y, b.z, b.w};
            #pragma unroll
            for (int i = 0; i < 4; i++)
                #pragma unroll
                for (int j = 0; j < 4; j++)
                    acc[i][j] += ar[i] * br[j];
        }
    }

    #pragma unroll
    for (int i = 0; i < 4; i++) {
        size_t base = (size_t)(row0 + m0 + i) * OFD + col0 + n0;
        *(float4*)(g_E + base) = make_float4(acc[i][0], acc[i][1], acc[i][2], acc[i][3]);
    }
}

// ---------------------------------------------------------------------------
// Kernel 3: per batch, att = tanh(E_b @ U_b^T); accumulate row/col sums.
// grid (4 r-tiles, 4 s-tiles, 64 batches), block 256
// ---------------------------------------------------------------------------
__global__ __launch_bounds__(256) void k_att(void)
{
    __shared__ float As[16][68];
    __shared__ float Bs[16][68];
    __shared__ float srow[64];
    __shared__ float scol[64];

    int b = blockIdx.z;
    int stile = blockIdx.y, rtile = blockIdx.x;
    int tid = threadIdx.x;
    int tx = tid & 15, ty = tid >> 4;
    int m0 = ty * 4, n0 = tx * 4;

    if (tid < 64) { srow[tid] = 0.0f; scol[tid] = 0.0f; }

    int lm = tid >> 2;
    int lk = (tid & 3) * 4;

    float acc[4][4] = {};
    gemm_acc_nmajor(g_E + (size_t)(b * SEQ + stile * 64 + lm) * OFD + lk,
                    g_U + (size_t)(b * SEQ + rtile * 64 + lm) * OFD + lk,
                    OFD, As, Bs, lk, lm, m0, n0, acc);

    float rsum[4] = {}, csum[4] = {};
    #pragma unroll
    for (int i = 0; i < 4; i++)
        #pragma unroll
        for (int j = 0; j < 4; j++) {
            float t = tanhf(acc[i][j]);
            rsum[i] += t;
            csum[j] += t;
        }

    // zero-init above is ordered before these atomics by the gemm's barriers
    #pragma unroll
    for (int i = 0; i < 4; i++) atomicAdd(&srow[m0 + i], rsum[i]);
    #pragma unroll
    for (int j = 0; j < 4; j++) atomicAdd(&scol[n0 + j], csum[j]);
    __syncthreads();

    if (tid < 64) {
        g_rowpart[(size_t)(b * SEQ + stile * 64 + tid) * 4 + rtile] = srow[tid];
        g_colpart[(size_t)(b * SEQ + rtile * 64 + tid) * 4 + stile] = scol[tid];
    }
}

// ---------------------------------------------------------------------------
// Kernel 4: softmax over the two mean vectors + weighted sums of D and U.
// grid (4 col-groups, 64 batches), block 128
// ---------------------------------------------------------------------------
__global__ __launch_bounds__(128) void k_out(float* __restrict__ out)
{
    int b = blockIdx.y;
    int cg = blockIdx.x;
    int tid = threadIdx.x;

    __shared__ float sd[256];
    __shared__ float su[256];
    __shared__ float red[128];

    for (int s = tid; s < 256; s += 128) {
        const float* rp = &g_rowpart[(size_t)(b * SEQ + s) * 4];
        sd[s] = (rp[0] + rp[1] + rp[2] + rp[3]) * (1.0f / 256.0f);
        const float* cp = &g_colpart[(size_t)(b * SEQ + s) * 4];
        su[s] = (cp[0] + cp[1] + cp[2] + cp[3]) * (1.0f / 256.0f);
    }
    __syncthreads();

    // softmax over sd
    {
        float v = fmaxf(sd[tid], sd[tid + 128]);
        red[tid] = v; __syncthreads();
        for (int off = 64; off > 0; off >>= 1) {
            if (tid < off) red[tid] = fmaxf(red[tid], red[tid + off]);
            __syncthreads();
        }
        float mx = red[0]; __syncthreads();
        float e0 = expf(sd[tid] - mx), e1 = expf(sd[tid + 128] - mx);
        red[tid] = e0 + e1; __syncthreads();
        for (int off = 64; off > 0; off >>= 1) {
            if (tid < off) red[tid] += red[tid + off];
            __syncthreads();
        }
        float inv = 1.0f / red[0]; __syncthreads();
        sd[tid] = e0 * inv; sd[tid + 128] = e1 * inv;
    }
    // softmax over su
    {
        __syncthreads();
        float v = fmaxf(su[tid], su[tid + 128]);
        red[tid] = v; __syncthreads();
        for (int off = 64; off > 0; off >>= 1) {
            if (tid < off) red[tid] = fmaxf(red[tid], red[tid + off]);
            __syncthreads();
        }
        float mx = red[0]; __syncthreads();
        float e0 = expf(su[tid] - mx), e1 = expf(su[tid + 128] - mx);
        red[tid] = e0 + e1; __syncthreads();
        for (int off = 64; off > 0; off >>= 1) {
            if (tid < off) red[tid] += red[tid + off];
            __syncthreads();
        }
        float inv = 1.0f / red[0]; __syncthreads();
        su[tid] = e0 * inv; su[tid + 128] = e1 * inv;
    }
    __syncthreads();

    int o = cg * 128 + tid;
    const float* Dp = g_D + (size_t)(b * SEQ) * OFD + o;
    const float* Up = g_U + (size_t)(b * SEQ) * OFD + o;
    float ad = 0.0f, au = 0.0f;
    #pragma unroll 4
    for (int s = 0; s < SEQ; s++) {
        ad += sd[s] * Dp[(size_t)s * OFD];
        au += su[s] * Up[(size_t)s * OFD];
    }
    out[(size_t)b * OFD + o] = ad;
    out[(size_t)BSZ * OFD + (size_t)b * OFD + o] = au;
}

extern "C" void kernel_launch(void* const* d_in, const int* in_sizes, int n_in,
                              void* d_out, int out_size)
{
    (void)in_sizes; (void)n_in; (void)out_size;
    const float* Xd = (const float*)d_in[0];
    const float* Xu = (const float*)d_in[1];
    const float* Wd = (const float*)d_in[2];
    const float* bd = (const float*)d_in[3];
    const float* Wu = (const float*)d_in[4];
    const float* bu = (const float*)d_in[5];
    const float* W  = (const float*)d_in[6];
    float* out = (float*)d_out;

    dim3 g1(OFD / 64, MROWS / 64);
    k_du<<<g1, 256>>>(Xd, Xu, Wd, bd, Wu, bu);
    k_e<<<g1, 256>>>(W);
    dim3 g3(4, 4, BSZ);
    k_att<<<g3, 256>>>();
    dim3 g4(4, BSZ);
    k_out<<<g4, 128>>>(out);
}

// round 7
// speedup vs baseline: 2.0716x; 2.0716x over previous
#include <cuda_runtime.h>
#include <cuda_bf16.h>
#include <cuda_pipeline.h>
#include <math.h>
#include <stdint.h>

#define BSZ 64
#define SEQ 256
#define MROWS (BSZ*SEQ)   // 16384
#define INF 1024
#define UFD 512
#define OFD 512

#define TILE_B  10240     // 128 rows x 80B (32 bf16 + 8 pad)
#define STAGE_B 40960     // 4 tiles (Ah, Al, Bh, Bl)
#define SMEM_GEMM (2*STAGE_B)         // 81920
#define SMEM_ATT  (2*STAGE_B + 1024)  // + srow/scol

// ---------------- scratch (__device__ globals; no runtime alloc) ----------------
__device__ __align__(16) float g_D[MROWS*OFD];   // raw then unused (pre-gating linear d)
__device__ __align__(16) float g_U[MROWS*OFD];
__device__ __align__(16) __nv_bfloat16 g_Xdh[MROWS*INF];
__device__ __align__(16) __nv_bfloat16 g_Xdl[MROWS*INF];
__device__ __align__(16) __nv_bfloat16 g_Xuh[MROWS*UFD];
__device__ __align__(16) __nv_bfloat16 g_Xul[MROWS*UFD];
__device__ __align__(16) __nv_bfloat16 g_Wdh[OFD*INF];
__device__ __align__(16) __nv_bfloat16 g_Wdl[OFD*INF];
__device__ __align__(16) __nv_bfloat16 g_Wuh[OFD*UFD];
__device__ __align__(16) __nv_bfloat16 g_Wul[OFD*UFD];
__device__ __align__(16) __nv_bfloat16 g_Wth[OFD*OFD];   // W^T: Wt[e][d] = W[d][e]
__device__ __align__(16) __nv_bfloat16 g_Wtl[OFD*OFD];
__device__ __align__(16) __nv_bfloat16 g_Dh[MROWS*OFD];  // gated d, split
__device__ __align__(16) __nv_bfloat16 g_Dl[MROWS*OFD];
__device__ __align__(16) __nv_bfloat16 g_Uh[MROWS*OFD];  // gated u, split
__device__ __align__(16) __nv_bfloat16 g_Ul[MROWS*OFD];
__device__ __align__(16) __nv_bfloat16 g_Eh[MROWS*OFD];
__device__ __align__(16) __nv_bfloat16 g_El[MROWS*OFD];
__device__ float g_rowpart[BSZ*SEQ*2];
__device__ float g_colpart[BSZ*SEQ*2];

// ---------------- helpers ----------------
__device__ __forceinline__ uint32_t smem_to_u32(const void* p) {
    uint32_t a;
    asm("{ .reg .u64 t; cvta.to.shared.u64 t, %1; cvt.u32.u64 %0, t; }" : "=r"(a) : "l"(p));
    return a;
}
__device__ __forceinline__ void ldmx4(uint32_t r[4], uint32_t addr) {
    asm volatile("ldmatrix.sync.aligned.m8n8.x4.shared.b16 {%0,%1,%2,%3}, [%4];"
        : "=r"(r[0]), "=r"(r[1]), "=r"(r[2]), "=r"(r[3]) : "r"(addr));
}
__device__ __forceinline__ void mma16816(float c[4], const uint32_t a[4], const uint32_t b[2]) {
    asm volatile("mma.sync.aligned.m16n8k16.row.col.f32.bf16.bf16.f32 "
        "{%0,%1,%2,%3}, {%4,%5,%6,%7}, {%8,%9}, {%0,%1,%2,%3};"
        : "+f"(c[0]), "+f"(c[1]), "+f"(c[2]), "+f"(c[3])
        : "r"(a[0]), "r"(a[1]), "r"(a[2]), "r"(a[3]), "r"(b[0]), "r"(b[1]));
}
__device__ __forceinline__ float sigm(float x) { return 1.0f / (1.0f + expf(-x)); }

__device__ __forceinline__ void pack2(float v0, float v1, uint32_t& hi, uint32_t& lo) {
    __nv_bfloat16 h0 = __float2bfloat16(v0), h1 = __float2bfloat16(v1);
    __nv_bfloat162 hh; hh.x = h0; hh.y = h1;
    __nv_bfloat162 ll;
    ll.x = __float2bfloat16(v0 - __bfloat162float(h0));
    ll.y = __float2bfloat16(v1 - __bfloat162float(h1));
    hi = *reinterpret_cast<uint32_t*>(&hh);
    lo = *reinterpret_cast<uint32_t*>(&ll);
}

// ---------------- mma mainloop: acc[4][4][4] += 3-term split A(128xK) * B(128xK)^T --------
// A, B row-major, k contiguous. BM=BN=128, BK=32, 8 warps (2x4), warp tile 64x32.
__device__ __forceinline__ void gemm_mma(
    const __nv_bfloat16* __restrict__ Ah, const __nv_bfloat16* __restrict__ Al, int lda,
    const __nv_bfloat16* __restrict__ Bh, const __nv_bfloat16* __restrict__ Bl, int ldb,
    int K, char* smem, float (&acc)[4][4][4])
{
    int tid = threadIdx.x;
    int lane = tid & 31, wid = tid >> 5;
    int wm = (wid & 1) * 64, wn = (wid >> 1) * 32;
    uint32_t sb = smem_to_u32(smem);

    auto fill = [&](int s, int k0) {
        #pragma unroll
        for (int t = 0; t < 4; t++) {
            const __nv_bfloat16* bp = (t == 0) ? Ah : (t == 1) ? Al : (t == 2) ? Bh : Bl;
            int ld = (t < 2) ? lda : ldb;
            #pragma unroll
            for (int h = 0; h < 2; h++) {
                int chunk = h * 256 + tid;          // 0..511
                int row = chunk >> 2, c4 = chunk & 3;
                __pipeline_memcpy_async(
                    smem + s * STAGE_B + t * TILE_B + row * 80 + c4 * 16,
                    bp + (size_t)row * ld + k0 + c4 * 8, 16);
            }
        }
        __pipeline_commit();
    };

    // per-lane ldmatrix address components
    uint32_t a_row = (uint32_t)(lane & 15);
    uint32_t a_ko  = (uint32_t)((lane >> 4) << 4);                       // bytes
    uint32_t b_row = (uint32_t)((lane & 7) + ((lane >> 4) << 3));
    uint32_t b_ko  = (uint32_t)(((lane >> 3) & 1) << 4);                 // bytes

    int nk = K >> 5;
    fill(0, 0);
    for (int kt = 0; kt < nk; kt++) {
        if (kt + 1 < nk) { fill((kt + 1) & 1, (kt + 1) * 32); __pipeline_wait_prior(1); }
        else             { __pipeline_wait_prior(0); }
        __syncthreads();

        uint32_t stg = sb + (uint32_t)((kt & 1) * STAGE_B);
        uint32_t aoff = stg + (wm + a_row) * 80 + a_ko;
        uint32_t boff = stg + 2 * TILE_B + (wn + b_row) * 80 + b_ko;
        #pragma unroll
        for (int kk = 0; kk < 2; kk++) {
            uint32_t kb = (uint32_t)(kk * 32);
            uint32_t ah[4][4], alr[4][4], bh[2][4], blr[2][4];
            #pragma unroll
            for (int mf = 0; mf < 4; mf++) {
                ldmx4(ah[mf],  aoff + mf * (16 * 80) + kb);
                ldmx4(alr[mf], aoff + TILE_B + mf * (16 * 80) + kb);
            }
            #pragma unroll
            for (int nf2 = 0; nf2 < 2; nf2++) {
                ldmx4(bh[nf2],  boff + nf2 * (16 * 80) + kb);
                ldmx4(blr[nf2], boff + TILE_B + nf2 * (16 * 80) + kb);
            }
            #pragma unroll
            for (int mf = 0; mf < 4; mf++)
                #pragma unroll
                for (int nf = 0; nf < 4; nf++) {
                    const uint32_t* bhp = &bh[nf >> 1][(nf & 1) * 2];
                    const uint32_t* blp = &blr[nf >> 1][(nf & 1) * 2];
                    mma16816(acc[mf][nf], ah[mf], bhp);
                    mma16816(acc[mf][nf], ah[mf], blp);
                    mma16816(acc[mf][nf], alr[mf], bhp);
                }
        }
        __syncthreads();
    }
}

// ===========================================================================
// Conversion kernels
// ===========================================================================
__global__ __launch_bounds__(256) void k_cvt(const float* __restrict__ src,
                                             __nv_bfloat16* __restrict__ hi,
                                             __nv_bfloat16* __restrict__ lo, int n)
{
    int i = (blockIdx.x * 256 + threadIdx.x) * 4;
    if (i >= n) return;
    float4 v = *(const float4*)(src + i);
    uint32_t h0, l0, h1, l1;
    pack2(v.x, v.y, h0, l0);
    pack2(v.z, v.w, h1, l1);
    *(uint2*)(hi + i) = make_uint2(h0, h1);
    *(uint2*)(lo + i) = make_uint2(l0, l1);
}

__global__ __launch_bounds__(256) void k_cvtT(const float* __restrict__ W)
{
    int idx = blockIdx.x * 256 + threadIdx.x;  // idx = e*512 + d
    int e = idx >> 9, d = idx & 511;
    float x = W[d * 512 + e];
    __nv_bfloat16 h = __float2bfloat16(x);
    g_Wth[idx] = h;
    g_Wtl[idx] = __float2bfloat16(x - __bfloat162float(h));
}

// ===========================================================================
// Linear GEMM: out = A*B^T + bias.  grid (4, 128), block 256
// ===========================================================================
__global__ __launch_bounds__(256, 1) void k_lin(
    const __nv_bfloat16* __restrict__ Ah, const __nv_bfloat16* __restrict__ Al, int lda,
    const __nv_bfloat16* __restrict__ Bh, const __nv_bfloat16* __restrict__ Bl, int ldb,
    int K, const float* __restrict__ bias, float* __restrict__ out)
{
    extern __shared__ __align__(16) char smem[];
    int row0 = blockIdx.y * 128, col0 = blockIdx.x * 128;
    float acc[4][4][4] = {};
    gemm_mma(Ah + (size_t)row0 * lda, Al + (size_t)row0 * lda, lda,
             Bh + (size_t)col0 * ldb, Bl + (size_t)col0 * ldb, ldb, K, smem, acc);

    int tid = threadIdx.x, lane = tid & 31, wid = tid >> 5;
    int wm = (wid & 1) * 64, wn = (wid >> 1) * 32;
    int rb = row0 + wm + (lane >> 2);
    int cb = col0 + wn + 2 * (lane & 3);
    #pragma unroll
    for (int nf = 0; nf < 4; nf++) {
        int c = cb + nf * 8;
        float b0 = bias[c], b1 = bias[c + 1];
        #pragma unroll
        for (int mf = 0; mf < 4; mf++)
            #pragma unroll
            for (int rr = 0; rr < 2; rr++) {
                int r = rb + mf * 16 + rr * 8;
                float2 v = make_float2(acc[mf][nf][rr * 2] + b0,
                                       acc[mf][nf][rr * 2 + 1] + b1);
                *(float2*)(out + (size_t)r * OFD + c) = v;
            }
    }
}

// ===========================================================================
// Gating: d1 = d0*sig(u0); u1 = u0*sig(d1); write bf16 splits.
// ===========================================================================
__global__ __launch_bounds__(256) void k_gate(void)
{
    int i = (blockIdx.x * 256 + threadIdx.x) * 4;
    float4 d4 = *(const float4*)(g_D + i);
    float4 u4 = *(const float4*)(g_U + i);
    float dv[4] = {d4.x, d4.y, d4.z, d4.w};
    float uv[4] = {u4.x, u4.y, u4.z, u4.w};
    #pragma unroll
    for (int j = 0; j < 4; j++) {
        float d1 = dv[j] * sigm(uv[j]);
        float u1 = uv[j] * sigm(d1);
        dv[j] = d1; uv[j] = u1;
    }
    uint32_t h0, l0, h1, l1;
    pack2(dv[0], dv[1], h0, l0); pack2(dv[2], dv[3], h1, l1);
    *(uint2*)(g_Dh + i) = make_uint2(h0, h1);
    *(uint2*)(g_Dl + i) = make_uint2(l0, l1);
    pack2(uv[0], uv[1], h0, l0); pack2(uv[2], uv[3], h1, l1);
    *(uint2*)(g_Uh + i) = make_uint2(h0, h1);
    *(uint2*)(g_Ul + i) = make_uint2(l0, l1);
}

// ===========================================================================
// E = D @ W (via W^T), write bf16 split.  grid (4, 128), block 256
// ===========================================================================
__global__ __launch_bounds__(256, 1) void k_e(void)
{
    extern __shared__ __align__(16) char smem[];
    int row0 = blockIdx.y * 128, col0 = blockIdx.x * 128;
    float acc[4][4][4] = {};
    gemm_mma(g_Dh + (size_t)row0 * OFD, g_Dl + (size_t)row0 * OFD, OFD,
             g_Wth + (size_t)col0 * OFD, g_Wtl + (size_t)col0 * OFD, OFD,
             OFD, smem, acc);

    int tid = threadIdx.x, lane = tid & 31, wid = tid >> 5;
    int wm = (wid & 1) * 64, wn = (wid >> 1) * 32;
    int rb = row0 + wm + (lane >> 2);
    int cb = col0 + wn + 2 * (lane & 3);
    #pragma unroll
    for (int mf = 0; mf < 4; mf++)
        #pragma unroll
        for (int nf = 0; nf < 4; nf++)
            #pragma unroll
            for (int rr = 0; rr < 2; rr++) {
                int r = rb + mf * 16 + rr * 8;
                int c = cb + nf * 8;
                uint32_t hi, lo;
                pack2(acc[mf][nf][rr * 2], acc[mf][nf][rr * 2 + 1], hi, lo);
                *(uint32_t*)(g_Eh + (size_t)r * OFD + c) = hi;
                *(uint32_t*)(g_El + (size_t)r * OFD + c) = lo;
            }
}

// ===========================================================================
// att tile = tanh(E_b @ U_b^T); row/col partial sums.  grid (2 rt, 2 st, 64 b)
// ===========================================================================
__global__ __launch_bounds__(256, 1) void k_att(void)
{
    extern __shared__ __align__(16) char smem[];
    float* srow = (float*)(smem + 2 * STAGE_B);
    float* scol = srow + 128;
    int b = blockIdx.z, st = blockIdx.y, rt = blockIdx.x;
    int tid = threadIdx.x;
    if (tid < 128) { srow[tid] = 0.0f; scol[tid] = 0.0f; }
    // ordered before atomics below by the mainloop's __syncthreads

    float acc[4][4][4] = {};
    size_t ar = (size_t)(b * SEQ + st * 128) * OFD;
    size_t br = (size_t)(b * SEQ + rt * 128) * OFD;
    gemm_mma(g_Eh + ar, g_El + ar, OFD, g_Uh + br, g_Ul + br, OFD, OFD, smem, acc);

    int lane = tid & 31, wid = tid >> 5;
    int wm = (wid & 1) * 64, wn = (wid >> 1) * 32;
    int rb = wm + (lane >> 2);
    int cb = wn + 2 * (lane & 3);

    float t[4][4][4];
    #pragma unroll
    for (int mf = 0; mf < 4; mf++)
        #pragma unroll
        for (int nf = 0; nf < 4; nf++)
            #pragma unroll
            for (int e = 0; e < 4; e++)
                t[mf][nf][e] = tanhf(acc[mf][nf][e]);

    #pragma unroll
    for (int mf = 0; mf < 4; mf++) {
        float s0 = 0.0f, s1 = 0.0f;
        #pragma unroll
        for (int nf = 0; nf < 4; nf++) {
            s0 += t[mf][nf][0] + t[mf][nf][1];
            s1 += t[mf][nf][2] + t[mf][nf][3];
        }
        atomicAdd(&srow[rb + mf * 16], s0);
        atomicAdd(&srow[rb + mf * 16 + 8], s1);
    }
    #pragma unroll
    for (int nf = 0; nf < 4; nf++) {
        float c0 = 0.0f, c1 = 0.0f;
        #pragma unroll
        for (int mf = 0; mf < 4; mf++) {
            c0 += t[mf][nf][0] + t[mf][nf][2];
            c1 += t[mf][nf][1] + t[mf][nf][3];
        }
        atomicAdd(&scol[cb + nf * 8], c0);
        atomicAdd(&scol[cb + nf * 8 + 1], c1);
    }
    __syncthreads();

    if (tid < 128) {
        g_rowpart[(size_t)(b * SEQ + st * 128 + tid) * 2 + rt] = srow[tid];
        g_colpart[(size_t)(b * SEQ + rt * 128 + tid) * 2 + st] = scol[tid];
    }
}

// ===========================================================================
// Softmax + weighted sums.  grid (8 colgrp, 64 b), block 256
// ===========================================================================
__global__ __launch_bounds__(256) void k_out(float* __restrict__ out)
{
    int b = blockIdx.y, cg = blockIdx.x, tid = threadIdx.x;
    __shared__ float sd[256], su[256], red[256], psd[256], psu[256];

    {
        const float* rp = &g_rowpart[(size_t)(b * SEQ + tid) * 2];
        sd[tid] = (rp[0] + rp[1]) * (1.0f / 256.0f);
        const float* cp = &g_colpart[(size_t)(b * SEQ + tid) * 2];
        su[tid] = (cp[0] + cp[1]) * (1.0f / 256.0f);
    }
    __syncthreads();

    // softmax sd
    {
        red[tid] = sd[tid]; __syncthreads();
        for (int off = 128; off > 0; off >>= 1) {
            if (tid < off) red[tid] = fmaxf(red[tid], red[tid + off]);
            __syncthreads();
        }
        float mx = red[0]; __syncthreads();
        float e = expf(sd[tid] - mx);
        red[tid] = e; __syncthreads();
        for (int off = 128; off > 0; off >>= 1) {
            if (tid < off) red[tid] += red[tid + off];
            __syncthreads();
        }
        float inv = 1.0f / red[0]; __syncthreads();
        sd[tid] = e * inv;
    }
    __syncthreads();
    // softmax su
    {
        red[tid] = su[tid]; __syncthreads();
        for (int off = 128; off > 0; off >>= 1) {
            if (tid < off) red[tid] = fmaxf(red[tid], red[tid + off]);
            __syncthreads();
        }
        float mx = red[0]; __syncthreads();
        float e = expf(su[tid] - mx);
        red[tid] = e; __syncthreads();
        for (int off = 128; off > 0; off >>= 1) {
            if (tid < off) red[tid] += red[tid + off];
            __syncthreads();
        }
        float inv = 1.0f / red[0]; __syncthreads();
        su[tid] = e * inv;
    }
    __syncthreads();

    int o = cg * 64 + (tid & 63);
    int sseg = tid >> 6;                 // 4 segments of 64 s each
    size_t base = (size_t)(b * SEQ + sseg * 64) * OFD + o;
    float ad = 0.0f, au = 0.0f;
    #pragma unroll 4
    for (int s = 0; s < 64; s++) {
        size_t idx = base + (size_t)s * OFD;
        float dval = __bfloat162float(g_Dh[idx]) + __bfloat162float(g_Dl[idx]);
        float uval = __bfloat162float(g_Uh[idx]) + __bfloat162float(g_Ul[idx]);
        ad += sd[sseg * 64 + s] * dval;
        au += su[sseg * 64 + s] * uval;
    }
    psd[tid] = ad; psu[tid] = au;
    __syncthreads();
    if (tid < 64) {
        float a = psd[tid] + psd[tid + 64] + psd[tid + 128] + psd[tid + 192];
        float u = psu[tid] + psu[tid + 64] + psu[tid + 128] + psu[tid + 192];
        out[(size_t)b * OFD + cg * 64 + tid] = a;
        out[(size_t)BSZ * OFD + (size_t)b * OFD + cg * 64 + tid] = u;
    }
}

// ===========================================================================
extern "C" void kernel_launch(void* const* d_in, const int* in_sizes, int n_in,
                              void* d_out, int out_size)
{
    (void)in_sizes; (void)n_in; (void)out_size;
    const float* Xd = (const float*)d_in[0];
    const float* Xu = (const float*)d_in[1];
    const float* Wd = (const float*)d_in[2];
    const float* bd = (const float*)d_in[3];
    const float* Wu = (const float*)d_in[4];
    const float* bu = (const float*)d_in[5];
    const float* W  = (const float*)d_in[6];
    float* out = (float*)d_out;

    void *pXdh, *pXdl, *pXuh, *pXul, *pWdh, *pWdl, *pWuh, *pWul, *pD, *pU;
    cudaGetSymbolAddress(&pXdh, g_Xdh); cudaGetSymbolAddress(&pXdl, g_Xdl);
    cudaGetSymbolAddress(&pXuh, g_Xuh); cudaGetSymbolAddress(&pXul, g_Xul);
    cudaGetSymbolAddress(&pWdh, g_Wdh); cudaGetSymbolAddress(&pWdl, g_Wdl);
    cudaGetSymbolAddress(&pWuh, g_Wuh); cudaGetSymbolAddress(&pWul, g_Wul);
    cudaGetSymbolAddress(&pD, g_D);     cudaGetSymbolAddress(&pU, g_U);

    cudaFuncSetAttribute(k_lin, cudaFuncAttributeMaxDynamicSharedMemorySize, SMEM_GEMM);
    cudaFuncSetAttribute(k_e,   cudaFuncAttributeMaxDynamicSharedMemorySize, SMEM_GEMM);
    cudaFuncSetAttribute(k_att, cudaFuncAttributeMaxDynamicSharedMemorySize, SMEM_ATT);

    k_cvt<<<MROWS*INF/1024, 256>>>(Xd, (__nv_bfloat16*)pXdh, (__nv_bfloat16*)pXdl, MROWS*INF);
    k_cvt<<<MROWS*UFD/1024, 256>>>(Xu, (__nv_bfloat16*)pXuh, (__nv_bfloat16*)pXul, MROWS*UFD);
    k_cvt<<<OFD*INF/1024, 256>>>(Wd, (__nv_bfloat16*)pWdh, (__nv_bfloat16*)pWdl, OFD*INF);
    k_cvt<<<OFD*UFD/1024, 256>>>(Wu, (__nv_bfloat16*)pWuh, (__nv_bfloat16*)pWul, OFD*UFD);
    k_cvtT<<<OFD*OFD/256, 256>>>(W);

    dim3 g1(OFD / 128, MROWS / 128);
    k_lin<<<g1, 256, SMEM_GEMM>>>((const __nv_bfloat16*)pXdh, (const __nv_bfloat16*)pXdl, INF,
                                  (const __nv_bfloat16*)pWdh, (const __nv_bfloat16*)pWdl, INF,
                                  INF, bd, (float*)pD);
    k_lin<<<g1, 256, SMEM_GEMM>>>((const __nv_bfloat16*)pXuh, (const __nv_bfloat16*)pXul, UFD,
                                  (const __nv_bfloat16*)pWuh, (const __nv_bfloat16*)pWul, UFD,
                                  UFD, bu, (float*)pU);
    k_gate<<<MROWS*OFD/1024, 256>>>();
    k_e<<<g1, 256, SMEM_GEMM>>>();
    dim3 g3(2, 2, BSZ);
    k_att<<<g3, 256, SMEM_ATT>>>();
    dim3 g4(8, BSZ);
    k_out<<<g4, 256>>>(out);
}

// round 8
// speedup vs baseline: 2.3032x; 1.1118x over previous
#include <cuda_runtime.h>
#include <cuda_bf16.h>
#include <cuda_pipeline.h>
#include <math.h>
#include <stdint.h>

#define BSZ 64
#define SEQ 256
#define MROWS (BSZ*SEQ)   // 16384
#define INF 1024
#define UFD 512
#define OFD 512

#define TILE_B  10240     // 128 rows x 80B (32 bf16 + 8 pad)
#define STAGE_B 40960     // 4 tiles (Ah, Al, Bh, Bl)
#define SMEM_GEMM (2*STAGE_B)         // 81920
#define SMEM_ATT  (2*STAGE_B + 1024)  // + srow/scol

// ---------------- scratch (__device__ globals; no runtime alloc) ----------------
__device__ __align__(16) float g_D[MROWS*OFD];   // pre-gating linear d
__device__ __align__(16) __nv_bfloat16 g_Xdh[MROWS*INF];
__device__ __align__(16) __nv_bfloat16 g_Xdl[MROWS*INF];
__device__ __align__(16) __nv_bfloat16 g_Xuh[MROWS*UFD];
__device__ __align__(16) __nv_bfloat16 g_Xul[MROWS*UFD];
__device__ __align__(16) __nv_bfloat16 g_Wdh[OFD*INF];
__device__ __align__(16) __nv_bfloat16 g_Wdl[OFD*INF];
__device__ __align__(16) __nv_bfloat16 g_Wuh[OFD*UFD];
__device__ __align__(16) __nv_bfloat16 g_Wul[OFD*UFD];
__device__ __align__(16) __nv_bfloat16 g_Wth[OFD*OFD];   // W^T: Wt[e][d] = W[d][e]
__device__ __align__(16) __nv_bfloat16 g_Wtl[OFD*OFD];
__device__ __align__(16) __nv_bfloat16 g_Dh[MROWS*OFD];  // gated d, split
__device__ __align__(16) __nv_bfloat16 g_Dl[MROWS*OFD];
__device__ __align__(16) __nv_bfloat16 g_Uh[MROWS*OFD];  // gated u, split
__device__ __align__(16) __nv_bfloat16 g_Ul[MROWS*OFD];
__device__ __align__(16) __nv_bfloat16 g_Eh[MROWS*OFD];
__device__ __align__(16) __nv_bfloat16 g_El[MROWS*OFD];
__device__ float g_rowpart[BSZ*SEQ*2];
__device__ float g_colpart[BSZ*SEQ*2];

// ---------------- helpers ----------------
__device__ __forceinline__ uint32_t smem_to_u32(const void* p) {
    uint32_t a;
    asm("{ .reg .u64 t; cvta.to.shared.u64 t, %1; cvt.u32.u64 %0, t; }" : "=r"(a) : "l"(p));
    return a;
}
__device__ __forceinline__ void ldmx4(uint32_t r[4], uint32_t addr) {
    asm volatile("ldmatrix.sync.aligned.m8n8.x4.shared.b16 {%0,%1,%2,%3}, [%4];"
        : "=r"(r[0]), "=r"(r[1]), "=r"(r[2]), "=r"(r[3]) : "r"(addr));
}
__device__ __forceinline__ void mma16816(float c[4], const uint32_t a[4], const uint32_t b[2]) {
    asm volatile("mma.sync.aligned.m16n8k16.row.col.f32.bf16.bf16.f32 "
        "{%0,%1,%2,%3}, {%4,%5,%6,%7}, {%8,%9}, {%0,%1,%2,%3};"
        : "+f"(c[0]), "+f"(c[1]), "+f"(c[2]), "+f"(c[3])
        : "r"(a[0]), "r"(a[1]), "r"(a[2]), "r"(a[3]), "r"(b[0]), "r"(b[1]));
}
__device__ __forceinline__ float sigm(float x) { return 1.0f / (1.0f + __expf(-x)); }

__device__ __forceinline__ void pack2(float v0, float v1, uint32_t& hi, uint32_t& lo) {
    __nv_bfloat16 h0 = __float2bfloat16(v0), h1 = __float2bfloat16(v1);
    __nv_bfloat162 hh; hh.x = h0; hh.y = h1;
    __nv_bfloat162 ll;
    ll.x = __float2bfloat16(v0 - __bfloat162float(h0));
    ll.y = __float2bfloat16(v1 - __bfloat162float(h1));
    hi = *reinterpret_cast<uint32_t*>(&hh);
    lo = *reinterpret_cast<uint32_t*>(&ll);
}

// ---------------- mma mainloop: acc[4][4][4] += 3-term split A(128xK) * B(128xK)^T --------
// A, B row-major, k contiguous. BM=BN=128, BK=32, 8 warps (2x4), warp tile 64x32.
// Register-economical ordering: B frags resident per kk, A frags loaded per mf.
__device__ __forceinline__ void gemm_mma(
    const __nv_bfloat16* __restrict__ Ah, const __nv_bfloat16* __restrict__ Al, int lda,
    const __nv_bfloat16* __restrict__ Bh, const __nv_bfloat16* __restrict__ Bl, int ldb,
    int K, char* smem, float (&acc)[4][4][4])
{
    int tid = threadIdx.x;
    int lane = tid & 31, wid = tid >> 5;
    int wm = (wid & 1) * 64, wn = (wid >> 1) * 32;
    uint32_t sb = smem_to_u32(smem);

    auto fill = [&](int s, int k0) {
        #pragma unroll
        for (int t = 0; t < 4; t++) {
            const __nv_bfloat16* bp = (t == 0) ? Ah : (t == 1) ? Al : (t == 2) ? Bh : Bl;
            int ld = (t < 2) ? lda : ldb;
            #pragma unroll
            for (int h = 0; h < 2; h++) {
                int chunk = h * 256 + tid;          // 0..511
                int row = chunk >> 2, c4 = chunk & 3;
                __pipeline_memcpy_async(
                    smem + s * STAGE_B + t * TILE_B + row * 80 + c4 * 16,
                    bp + (size_t)row * ld + k0 + c4 * 8, 16);
            }
        }
        __pipeline_commit();
    };

    // per-lane ldmatrix address components
    uint32_t a_row = (uint32_t)(lane & 15);
    uint32_t a_ko  = (uint32_t)((lane >> 4) << 4);                       // bytes
    uint32_t b_row = (uint32_t)((lane & 7) + ((lane >> 4) << 3));
    uint32_t b_ko  = (uint32_t)(((lane >> 3) & 1) << 4);                 // bytes

    int nk = K >> 5;
    fill(0, 0);
    for (int kt = 0; kt < nk; kt++) {
        if (kt + 1 < nk) { fill((kt + 1) & 1, (kt + 1) * 32); __pipeline_wait_prior(1); }
        else             { __pipeline_wait_prior(0); }
        __syncthreads();

        uint32_t stg = sb + (uint32_t)((kt & 1) * STAGE_B);
        uint32_t aoff = stg + (wm + a_row) * 80 + a_ko;
        uint32_t boff = stg + 2 * TILE_B + (wn + b_row) * 80 + b_ko;
        #pragma unroll
        for (int kk = 0; kk < 2; kk++) {
            uint32_t kb = (uint32_t)(kk * 32);
            uint32_t bh[2][4], blr[2][4];
            #pragma unroll
            for (int nf2 = 0; nf2 < 2; nf2++) {
                ldmx4(bh[nf2],  boff + nf2 * (16 * 80) + kb);
                ldmx4(blr[nf2], boff + TILE_B + nf2 * (16 * 80) + kb);
            }
            #pragma unroll
            for (int mf = 0; mf < 4; mf++) {
                uint32_t ah[4], alr[4];
                ldmx4(ah,  aoff + mf * (16 * 80) + kb);
                ldmx4(alr, aoff + TILE_B + mf * (16 * 80) + kb);
                #pragma unroll
                for (int nf = 0; nf < 4; nf++) {
                    const uint32_t* bhp = &bh[nf >> 1][(nf & 1) * 2];
                    const uint32_t* blp = &blr[nf >> 1][(nf & 1) * 2];
                    mma16816(acc[mf][nf], ah, bhp);
                    mma16816(acc[mf][nf], ah, blp);
                    mma16816(acc[mf][nf], alr, bhp);
                }
            }
        }
        __syncthreads();
    }
}

// ===========================================================================
// Conversion kernels
// ===========================================================================
__global__ __launch_bounds__(256) void k_cvt(const float* __restrict__ src,
                                             __nv_bfloat16* __restrict__ hi,
                                             __nv_bfloat16* __restrict__ lo, int n)
{
    int i = (blockIdx.x * 256 + threadIdx.x) * 4;
    if (i >= n) return;
    float4 v = *(const float4*)(src + i);
    uint32_t h0, l0, h1, l1;
    pack2(v.x, v.y, h0, l0);
    pack2(v.z, v.w, h1, l1);
    *(uint2*)(hi + i) = make_uint2(h0, h1);
    *(uint2*)(lo + i) = make_uint2(l0, l1);
}

__global__ __launch_bounds__(256) void k_cvtT(const float* __restrict__ W)
{
    int idx = blockIdx.x * 256 + threadIdx.x;  // idx = e*512 + d
    int e = idx >> 9, d = idx & 511;
    float x = W[d * 512 + e];
    __nv_bfloat16 h = __float2bfloat16(x);
    g_Wth[idx] = h;
    g_Wtl[idx] = __float2bfloat16(x - __bfloat162float(h));
}

// ===========================================================================
// d-GEMM: g_D = Xd*Wd^T + bd (fp32).  grid (4, 128), block 256
// ===========================================================================
__global__ __launch_bounds__(256, 2) void k_lin_d(const float* __restrict__ bias)
{
    extern __shared__ __align__(16) char smem[];
    int row0 = blockIdx.y * 128, col0 = blockIdx.x * 128;
    float acc[4][4][4] = {};
    gemm_mma(g_Xdh + (size_t)row0 * INF, g_Xdl + (size_t)row0 * INF, INF,
             g_Wdh + (size_t)col0 * INF, g_Wdl + (size_t)col0 * INF, INF,
             INF, smem, acc);

    int tid = threadIdx.x, lane = tid & 31, wid = tid >> 5;
    int wm = (wid & 1) * 64, wn = (wid >> 1) * 32;
    int rb = row0 + wm + (lane >> 2);
    int cb = col0 + wn + 2 * (lane & 3);
    #pragma unroll
    for (int nf = 0; nf < 4; nf++) {
        int c = cb + nf * 8;
        float b0 = bias[c], b1 = bias[c + 1];
        #pragma unroll
        for (int mf = 0; mf < 4; mf++)
            #pragma unroll
            for (int rr = 0; rr < 2; rr++) {
                int r = rb + mf * 16 + rr * 8;
                *(float2*)(g_D + (size_t)r * OFD + c) =
                    make_float2(acc[mf][nf][rr * 2] + b0, acc[mf][nf][rr * 2 + 1] + b1);
            }
    }
}

// ===========================================================================
// u-GEMM + fused gating: u0 = Xu*Wu^T + bu; d1 = d0*sig(u0); u1 = u0*sig(d1);
// writes bf16 splits of d1, u1.  grid (4, 128), block 256
// ===========================================================================
__global__ __launch_bounds__(256, 2) void k_lin_u(const float* __restrict__ bias)
{
    extern __shared__ __align__(16) char smem[];
    int row0 = blockIdx.y * 128, col0 = blockIdx.x * 128;
    float acc[4][4][4] = {};
    gemm_mma(g_Xuh + (size_t)row0 * UFD, g_Xul + (size_t)row0 * UFD, UFD,
             g_Wuh + (size_t)col0 * UFD, g_Wul + (size_t)col0 * UFD, UFD,
             UFD, smem, acc);

    int tid = threadIdx.x, lane = tid & 31, wid = tid >> 5;
    int wm = (wid & 1) * 64, wn = (wid >> 1) * 32;
    int rb = row0 + wm + (lane >> 2);
    int cb = col0 + wn + 2 * (lane & 3);
    #pragma unroll
    for (int nf = 0; nf < 4; nf++) {
        int c = cb + nf * 8;
        float b0 = bias[c], b1 = bias[c + 1];
        #pragma unroll
        for (int mf = 0; mf < 4; mf++)
            #pragma unroll
            for (int rr = 0; rr < 2; rr++) {
                int r = rb + mf * 16 + rr * 8;
                size_t idx = (size_t)r * OFD + c;
                float2 d4 = *(const float2*)(g_D + idx);
                float u00 = acc[mf][nf][rr * 2]     + b0;
                float u01 = acc[mf][nf][rr * 2 + 1] + b1;
                float d10 = d4.x * sigm(u00);
                float d11 = d4.y * sigm(u01);
                float u10 = u00 * sigm(d10);
                float u11 = u01 * sigm(d11);
                uint32_t hi, lo;
                pack2(d10, d11, hi, lo);
                *(uint32_t*)(g_Dh + idx) = hi;
                *(uint32_t*)(g_Dl + idx) = lo;
                pack2(u10, u11, hi, lo);
                *(uint32_t*)(g_Uh + idx) = hi;
                *(uint32_t*)(g_Ul + idx) = lo;
            }
    }
}

// ===========================================================================
// E = D @ W (via W^T), write bf16 split.  grid (4, 128), block 256
// ===========================================================================
__global__ __launch_bounds__(256, 2) void k_e(void)
{
    extern __shared__ __align__(16) char smem[];
    int row0 = blockIdx.y * 128, col0 = blockIdx.x * 128;
    float acc[4][4][4] = {};
    gemm_mma(g_Dh + (size_t)row0 * OFD, g_Dl + (size_t)row0 * OFD, OFD,
             g_Wth + (size_t)col0 * OFD, g_Wtl + (size_t)col0 * OFD, OFD,
             OFD, smem, acc);

    int tid = threadIdx.x, lane = tid & 31, wid = tid >> 5;
    int wm = (wid & 1) * 64, wn = (wid >> 1) * 32;
    int rb = row0 + wm + (lane >> 2);
    int cb = col0 + wn + 2 * (lane & 3);
    #pragma unroll
    for (int mf = 0; mf < 4; mf++)
        #pragma unroll
        for (int nf = 0; nf < 4; nf++)
            #pragma unroll
            for (int rr = 0; rr < 2; rr++) {
                int r = rb + mf * 16 + rr * 8;
                int c = cb + nf * 8;
                uint32_t hi, lo;
                pack2(acc[mf][nf][rr * 2], acc[mf][nf][rr * 2 + 1], hi, lo);
                *(uint32_t*)(g_Eh + (size_t)r * OFD + c) = hi;
                *(uint32_t*)(g_El + (size_t)r * OFD + c) = lo;
            }
}

// ===========================================================================
// att tile = tanh(E_b @ U_b^T); row/col partial sums.  grid (2 rt, 2 st, 64 b)
// ===========================================================================
__global__ __launch_bounds__(256, 2) void k_att(void)
{
    extern __shared__ __align__(16) char smem[];
    float* srow = (float*)(smem + 2 * STAGE_B);
    float* scol = srow + 128;
    int b = blockIdx.z, st = blockIdx.y, rt = blockIdx.x;
    int tid = threadIdx.x;
    if (tid < 128) { srow[tid] = 0.0f; scol[tid] = 0.0f; }
    // ordered before atomics below by the mainloop's __syncthreads

    float acc[4][4][4] = {};
    size_t ar = (size_t)(b * SEQ + st * 128) * OFD;
    size_t br = (size_t)(b * SEQ + rt * 128) * OFD;
    gemm_mma(g_Eh + ar, g_El + ar, OFD, g_Uh + br, g_Ul + br, OFD, OFD, smem, acc);

    int lane = tid & 31, wid = tid >> 5;
    int wm = (wid & 1) * 64, wn = (wid >> 1) * 32;
    int rb = wm + (lane >> 2);
    int cb = wn + 2 * (lane & 3);

    float t[4][4][4];
    #pragma unroll
    for (int mf = 0; mf < 4; mf++)
        #pragma unroll
        for (int nf = 0; nf < 4; nf++)
            #pragma unroll
            for (int e = 0; e < 4; e++)
                t[mf][nf][e] = tanhf(acc[mf][nf][e]);

    #pragma unroll
    for (int mf = 0; mf < 4; mf++) {
        float s0 = 0.0f, s1 = 0.0f;
        #pragma unroll
        for (int nf = 0; nf < 4; nf++) {
            s0 += t[mf][nf][0] + t[mf][nf][1];
            s1 += t[mf][nf][2] + t[mf][nf][3];
        }
        atomicAdd(&srow[rb + mf * 16], s0);
        atomicAdd(&srow[rb + mf * 16 + 8], s1);
    }
    #pragma unroll
    for (int nf = 0; nf < 4; nf++) {
        float c0 = 0.0f, c1 = 0.0f;
        #pragma unroll
        for (int mf = 0; mf < 4; mf++) {
            c0 += t[mf][nf][0] + t[mf][nf][2];
            c1 += t[mf][nf][1] + t[mf][nf][3];
        }
        atomicAdd(&scol[cb + nf * 8], c0);
        atomicAdd(&scol[cb + nf * 8 + 1], c1);
    }
    __syncthreads();

    if (tid < 128) {
        g_rowpart[(size_t)(b * SEQ + st * 128 + tid) * 2 + rt] = srow[tid];
        g_colpart[(size_t)(b * SEQ + rt * 128 + tid) * 2 + st] = scol[tid];
    }
}

// ===========================================================================
// Softmax + weighted sums.  grid (8 colgrp, 64 b), block 256
// ===========================================================================
__global__ __launch_bounds__(256) void k_out(float* __restrict__ out)
{
    int b = blockIdx.y, cg = blockIdx.x, tid = threadIdx.x;
    __shared__ float sd[256], su[256], red[256], psd[256], psu[256];

    {
        const float* rp = &g_rowpart[(size_t)(b * SEQ + tid) * 2];
        sd[tid] = (rp[0] + rp[1]) * (1.0f / 256.0f);
        const float* cp = &g_colpart[(size_t)(b * SEQ + tid) * 2];
        su[tid] = (cp[0] + cp[1]) * (1.0f / 256.0f);
    }
    __syncthreads();

    // softmax sd
    {
        red[tid] = sd[tid]; __syncthreads();
        for (int off = 128; off > 0; off >>= 1) {
            if (tid < off) red[tid] = fmaxf(red[tid], red[tid + off]);
            __syncthreads();
        }
        float mx = red[0]; __syncthreads();
        float e = expf(sd[tid] - mx);
        red[tid] = e; __syncthreads();
        for (int off = 128; off > 0; off >>= 1) {
            if (tid < off) red[tid] += red[tid + off];
            __syncthreads();
        }
        float inv = 1.0f / red[0]; __syncthreads();
        sd[tid] = e * inv;
    }
    __syncthreads();
    // softmax su
    {
        red[tid] = su[tid]; __syncthreads();
        for (int off = 128; off > 0; off >>= 1) {
            if (tid < off) red[tid] = fmaxf(red[tid], red[tid + off]);
            __syncthreads();
        }
        float mx = red[0]; __syncthreads();
        float e = expf(su[tid] - mx);
        red[tid] = e; __syncthreads();
        for (int off = 128; off > 0; off >>= 1) {
            if (tid < off) red[tid] += red[tid + off];
            __syncthreads();
        }
        float inv = 1.0f / red[0]; __syncthreads();
        su[tid] = e * inv;
    }
    __syncthreads();

    int o = cg * 64 + (tid & 63);
    int sseg = tid >> 6;                 // 4 segments of 64 s each
    size_t base = (size_t)(b * SEQ + sseg * 64) * OFD + o;
    float ad = 0.0f, au = 0.0f;
    #pragma unroll 4
    for (int s = 0; s < 64; s++) {
        size_t idx = base + (size_t)s * OFD;
        float dval = __bfloat162float(g_Dh[idx]) + __bfloat162float(g_Dl[idx]);
        float uval = __bfloat162float(g_Uh[idx]) + __bfloat162float(g_Ul[idx]);
        ad += sd[sseg * 64 + s] * dval;
        au += su[sseg * 64 + s] * uval;
    }
    psd[tid] = ad; psu[tid] = au;
    __syncthreads();
    if (tid < 64) {
        float a = psd[tid] + psd[tid + 64] + psd[tid + 128] + psd[tid + 192];
        float u = psu[tid] + psu[tid + 64] + psu[tid + 128] + psu[tid + 192];
        out[(size_t)b * OFD + cg * 64 + tid] = a;
        out[(size_t)BSZ * OFD + (size_t)b * OFD + cg * 64 + tid] = u;
    }
}

// ===========================================================================
extern "C" void kernel_launch(void* const* d_in, const int* in_sizes, int n_in,
                              void* d_out, int out_size)
{
    (void)in_sizes; (void)n_in; (void)out_size;
    const float* Xd = (const float*)d_in[0];
    const float* Xu = (const float*)d_in[1];
    const float* Wd = (const float*)d_in[2];
    const float* bd = (const float*)d_in[3];
    const float* Wu = (const float*)d_in[4];
    const float* bu = (const float*)d_in[5];
    const float* W  = (const float*)d_in[6];
    float* out = (float*)d_out;

    void *pXdh, *pXdl, *pXuh, *pXul, *pWdh, *pWdl, *pWuh, *pWul;
    cudaGetSymbolAddress(&pXdh, g_Xdh); cudaGetSymbolAddress(&pXdl, g_Xdl);
    cudaGetSymbolAddress(&pXuh, g_Xuh); cudaGetSymbolAddress(&pXul, g_Xul);
    cudaGetSymbolAddress(&pWdh, g_Wdh); cudaGetSymbolAddress(&pWdl, g_Wdl);
    cudaGetSymbolAddress(&pWuh, g_Wuh); cudaGetSymbolAddress(&pWul, g_Wul);

    cudaFuncSetAttribute(k_lin_d, cudaFuncAttributeMaxDynamicSharedMemorySize, SMEM_GEMM);
    cudaFuncSetAttribute(k_lin_u, cudaFuncAttributeMaxDynamicSharedMemorySize, SMEM_GEMM);
    cudaFuncSetAttribute(k_e,     cudaFuncAttributeMaxDynamicSharedMemorySize, SMEM_GEMM);
    cudaFuncSetAttribute(k_att,   cudaFuncAttributeMaxDynamicSharedMemorySize, SMEM_ATT);

    k_cvt<<<MROWS*INF/1024, 256>>>(Xd, (__nv_bfloat16*)pXdh, (__nv_bfloat16*)pXdl, MROWS*INF);
    k_cvt<<<MROWS*UFD/1024, 256>>>(Xu, (__nv_bfloat16*)pXuh, (__nv_bfloat16*)pXul, MROWS*UFD);
    k_cvt<<<OFD*INF/1024, 256>>>(Wd, (__nv_bfloat16*)pWdh, (__nv_bfloat16*)pWdl, OFD*INF);
    k_cvt<<<OFD*UFD/1024, 256>>>(Wu, (__nv_bfloat16*)pWuh, (__nv_bfloat16*)pWul, OFD*UFD);
    k_cvtT<<<OFD*OFD/256, 256>>>(W);

    dim3 g1(OFD / 128, MROWS / 128);
    k_lin_d<<<g1, 256, SMEM_GEMM>>>(bd);
    k_lin_u<<<g1, 256, SMEM_GEMM>>>(bu);
    k_e<<<g1, 256, SMEM_GEMM>>>();
    dim3 g3(2, 2, BSZ);
    k_att<<<g3, 256, SMEM_ATT>>>();
    dim3 g4(8, BSZ);
    k_out<<<g4, 256>>>(out);
}